// round 14
// baseline (speedup 1.0000x reference)
#include <cuda_runtime.h>
#include <cuda_fp16.h>
#include <math.h>

// Problem constants
#define B   64
#define T   100
#define S   1024
#define IN  256
#define TRG 512
#define ENC 512
#define G4  2048   // 4*TRG

// Output layout offsets (floats)
#define OUT_OFF   0
#define HT_OFF    3276800
#define CT_OFF    3309568
#define HAT_OFF   3342336
#define ATTN_OFF  3375104
#define PAT_OFF   9928704
#define PGEN_OFF  9994240
#define PDH_OFF   10000640
#define LOSS_OFF  10033408

// ---------------- device state ----------------
__device__ __align__(16) __half  g_encproj_h[(size_t)B * S * TRG];   // 67 MB
__device__ __align__(16) __half  g_enc_h[(size_t)B * S * ENC];       // 67 MB
__device__ __align__(16) __half  g_wen_h[512 * 512];
__device__ __align__(16) __half  g_input_h[B * T * IN];
__device__ __align__(16) __half  g_wihx_h[G4 * IN];
__device__ __align__(16) __half  g_wr_h[(size_t)G4 * 1024];
__device__ __align__(16) __half  g_wde_h[TRG * TRG];
__device__ __align__(16) __half  g_x_h[B * 1024];                    // [ha | h] fp16
__device__ __align__(16) float   g_xg[(size_t)B * T * G4];
__device__ __align__(16) float g_h[B * TRG];
__device__ __align__(16) float g_c[2][B * TRG];                      // double-buffered
__device__ __align__(16) float g_ha[B * TRG];
__device__ __align__(16) float g_pa[B * S];
__device__ __align__(16) float g_gp8[8][B * G4];                     // gates split-K partials
__device__ __align__(16) float g_hde4[4][B * TRG];                   // hde split-K partials
__device__ __align__(16) float g_attn[B * S];                        // unnormalized chunk exps
__device__ __align__(16) float g_pm[B * 16];                         // chunk max
__device__ __align__(16) float g_ps[B * 16];                         // chunk expsum
__device__ __align__(16) float g_cencP[16][B * TRG];                 // cenc chunk partials

__device__ __forceinline__ float warp_red_sum(float v) {
#pragma unroll
    for (int o = 16; o; o >>= 1) v += __shfl_xor_sync(0xffffffffu, v, o);
    return v;
}
__device__ __forceinline__ float sigmoidf_(float x) { return 1.0f / (1.0f + expf(-x)); }
__device__ __forceinline__ float tanh_ap(float x) {
    float y; asm("tanh.approx.f32 %0, %1;" : "=f"(y) : "f"(x)); return y;
}
__device__ __forceinline__ unsigned smem_u32(const void* p) {
    return (unsigned)__cvta_generic_to_shared(p);
}

// ---------------- merged setup ----------------
#define SEG_A 8388608u
#define SEG_B (SEG_A + 65536u)
#define SEG_C (SEG_B + 409600u)
#define SEG_D (SEG_C + 65536u)
#define SEG_E (SEG_D + 131072u)
#define SEG_F (SEG_E + 524288u)
#define SEG_G (SEG_F + 8192u)
#define SEG_H (SEG_G + 16384u)

__device__ __forceinline__ void f2h_unit(const float* __restrict__ src,
                                         __half* __restrict__ dst, unsigned u) {
    float4 v = *(const float4*)&src[(size_t)u * 4];
    __half2* d = (__half2*)&dst[(size_t)u * 4];
    d[0] = __floats2half2_rn(v.x, v.y);
    d[1] = __floats2half2_rn(v.z, v.w);
}

__global__ void k_setup(const float* __restrict__ enc, const float* __restrict__ w_en,
                        const float* __restrict__ input_, const float* __restrict__ w_de,
                        const float* __restrict__ w_ih, const float* __restrict__ w_hh,
                        const float* __restrict__ h0, const float* __restrict__ c0,
                        const float* __restrict__ h_attn, const float* __restrict__ past_attn) {
    for (unsigned u = blockIdx.x * blockDim.x + threadIdx.x; u < SEG_H;
         u += gridDim.x * blockDim.x) {
        if (u < SEG_A) {
            f2h_unit(enc, g_enc_h, u);
        } else if (u < SEG_B) {
            f2h_unit(w_en, g_wen_h, u - SEG_A);
        } else if (u < SEG_C) {
            f2h_unit(input_, g_input_h, u - SEG_B);
        } else if (u < SEG_D) {
            f2h_unit(w_de, g_wde_h, u - SEG_C);
        } else if (u < SEG_E) {
            unsigned v = u - SEG_D;
            unsigned n = v >> 6, c4 = (v & 63u) * 4;
            float4 w = *(const float4*)&w_ih[(size_t)n * (IN + TRG) + c4];
            __half2* d = (__half2*)&g_wihx_h[n * IN + c4];
            d[0] = __floats2half2_rn(w.x, w.y);
            d[1] = __floats2half2_rn(w.z, w.w);
        } else if (u < SEG_F) {
            unsigned v = u - SEG_E;
            unsigned n = v >> 8, k4 = (v & 255u) * 4;
            float4 w = (k4 < TRG) ? *(const float4*)&w_ih[(size_t)n * (IN + TRG) + IN + k4]
                                  : *(const float4*)&w_hh[(size_t)n * TRG + k4 - TRG];
            __half2* d = (__half2*)&g_wr_h[(size_t)n * 1024 + k4];
            d[0] = __floats2half2_rn(w.x, w.y);
            d[1] = __floats2half2_rn(w.z, w.w);
        } else if (u < SEG_G) {
            unsigned v = u - SEG_F;
#pragma unroll
            for (int e = 0; e < 4; e++) {
                int i = v * 4 + e;
                float hv = h0[i], cv = c0[i], av = h_attn[i];
                g_h[i] = hv; g_c[0][i] = cv; g_ha[i] = av;
                int b = i >> 9, j = i & 511;
                g_x_h[b * 1024 + j]       = __float2half_rn(av);
                g_x_h[b * 1024 + 512 + j] = __float2half_rn(hv);
            }
        } else {
            unsigned v = u - SEG_G;
            *(float4*)&g_pa[v * 4] = *(const float4*)&past_attn[v * 4];
        }
    }
}

// ---------------- setup fp16 TC GEMM (encproj, xg) ----------------
template<bool OUT16>
__global__ void k_mma(const __half* __restrict__ A, const __half* __restrict__ W,
                      const float* __restrict__ bias, void* __restrict__ Cout,
                      int K, int ldc) {
    __shared__ __align__(16) char smem_raw[128 * 68 * 4];
    __shared__ float sBias[64];
    __half (*sA)[72] = (__half(*)[72])smem_raw;
    __half (*sB)[72] = (__half(*)[72])(smem_raw + 18432);

    const int m0 = blockIdx.y * 128;
    const int n0 = blockIdx.x * 64;
    const int tid = threadIdx.x;
    const int lane = tid & 31;
    const int w = tid >> 5;
    const int wm = (w >> 1) * 32;
    const int wn = (w & 1) * 32;

    if (OUT16 && tid < 64) sBias[tid] = bias[n0 + tid];

    float c[2][4][4];
#pragma unroll
    for (int i = 0; i < 2; i++)
#pragma unroll
        for (int j = 0; j < 4; j++)
#pragma unroll
            for (int q = 0; q < 4; q++) c[i][j][q] = 0.f;

    const int lrow = lane & 15;
    const int lcol = (lane >> 4) * 8;

    for (int k0 = 0; k0 < K; k0 += 64) {
        __syncthreads();
        {
            int r = tid >> 3, cc = (tid & 7) * 8;
#pragma unroll
            for (int p = 0; p < 4; p++)
                *(float4*)&sA[r + p * 32][cc] =
                    *(const float4*)&A[(size_t)(m0 + r + p * 32) * K + k0 + cc];
#pragma unroll
            for (int p = 0; p < 2; p++)
                *(float4*)&sB[r + p * 32][cc] =
                    *(const float4*)&W[(size_t)(n0 + r + p * 32) * K + k0 + cc];
        }
        __syncthreads();
#pragma unroll
        for (int kk = 0; kk < 4; kk++) {
            unsigned a[2][4], bf[4][2];
#pragma unroll
            for (int mt = 0; mt < 2; mt++) {
                unsigned addr = smem_u32(&sA[wm + mt * 16 + lrow][kk * 16 + lcol]);
                asm volatile("ldmatrix.sync.aligned.m8n8.x4.shared.b16 {%0,%1,%2,%3}, [%4];"
                             : "=r"(a[mt][0]), "=r"(a[mt][1]), "=r"(a[mt][2]), "=r"(a[mt][3])
                             : "r"(addr));
            }
#pragma unroll
            for (int bp = 0; bp < 2; bp++) {
                unsigned r0, r1, r2, r3;
                unsigned addr = smem_u32(&sB[wn + bp * 16 + lrow][kk * 16 + lcol]);
                asm volatile("ldmatrix.sync.aligned.m8n8.x4.shared.b16 {%0,%1,%2,%3}, [%4];"
                             : "=r"(r0), "=r"(r1), "=r"(r2), "=r"(r3) : "r"(addr));
                bf[bp * 2 + 0][0] = r0; bf[bp * 2 + 0][1] = r2;
                bf[bp * 2 + 1][0] = r1; bf[bp * 2 + 1][1] = r3;
            }
#pragma unroll
            for (int mt = 0; mt < 2; mt++)
#pragma unroll
                for (int nf = 0; nf < 4; nf++) {
                    asm volatile(
                        "mma.sync.aligned.m16n8k16.row.col.f32.f16.f16.f32 "
                        "{%0,%1,%2,%3}, {%4,%5,%6,%7}, {%8,%9}, {%0,%1,%2,%3};"
                        : "+f"(c[mt][nf][0]), "+f"(c[mt][nf][1]),
                          "+f"(c[mt][nf][2]), "+f"(c[mt][nf][3])
                        : "r"(a[mt][0]), "r"(a[mt][1]), "r"(a[mt][2]), "r"(a[mt][3]),
                          "r"(bf[nf][0]), "r"(bf[nf][1]));
                }
        }
    }
    __syncthreads();
    float (*sO)[68] = (float(*)[68])smem_raw;
    {
        int g = lane >> 2, tq = lane & 3;
#pragma unroll
        for (int mt = 0; mt < 2; mt++)
#pragma unroll
            for (int nf = 0; nf < 4; nf++) {
                int r = wm + mt * 16 + g;
                int cc = wn + (nf >> 1) * 16 + (nf & 1) * 8 + tq * 2;
                sO[r][cc]     = c[mt][nf][0]; sO[r][cc + 1]     = c[mt][nf][1];
                sO[r + 8][cc] = c[mt][nf][2]; sO[r + 8][cc + 1] = c[mt][nf][3];
            }
    }
    __syncthreads();
#pragma unroll
    for (int p = 0; p < 4; p++) {
        int idx = p * 256 + tid;
        int r = idx >> 3, c8 = (idx & 7) * 8;
        if (OUT16) {
            __half* C = (__half*)Cout;
            __half2 h[4];
#pragma unroll
            for (int q = 0; q < 4; q++)
                h[q] = __floats2half2_rn(sO[r][c8 + 2 * q] + sBias[c8 + 2 * q],
                                         sO[r][c8 + 2 * q + 1] + sBias[c8 + 2 * q + 1]);
            *(float4*)&C[(size_t)(m0 + r) * ldc + n0 + c8] = *(float4*)h;
        } else {
            float* C = (float*)Cout;
            *(float4*)&C[(size_t)(m0 + r) * ldc + n0 + c8]     = *(float4*)&sO[r][c8];
            *(float4*)&C[(size_t)(m0 + r) * ldc + n0 + c8 + 4] = *(float4*)&sO[r][c8 + 4];
        }
    }
}

// ---------------- shared mma helpers ----------------
__device__ __forceinline__ void mma_slab(const __half (*sA)[72], const __half (*sB)[72],
                                         int wm, int wn, int lane, float c[2][2][4]) {
    const int lrow = lane & 15;
    const int lcol = (lane >> 4) * 8;
#pragma unroll
    for (int kk = 0; kk < 4; kk++) {
        unsigned a[2][4], bf[2][2];
#pragma unroll
        for (int mt = 0; mt < 2; mt++) {
            unsigned addr = smem_u32(&sA[wm + mt * 16 + lrow][kk * 16 + lcol]);
            asm volatile("ldmatrix.sync.aligned.m8n8.x4.shared.b16 {%0,%1,%2,%3}, [%4];"
                         : "=r"(a[mt][0]), "=r"(a[mt][1]), "=r"(a[mt][2]), "=r"(a[mt][3])
                         : "r"(addr));
        }
        {
            unsigned r0, r1, r2, r3;
            unsigned addr = smem_u32(&sB[wn + lrow][kk * 16 + lcol]);
            asm volatile("ldmatrix.sync.aligned.m8n8.x4.shared.b16 {%0,%1,%2,%3}, [%4];"
                         : "=r"(r0), "=r"(r1), "=r"(r2), "=r"(r3) : "r"(addr));
            bf[0][0] = r0; bf[0][1] = r2;
            bf[1][0] = r1; bf[1][1] = r3;
        }
#pragma unroll
        for (int mt = 0; mt < 2; mt++)
#pragma unroll
            for (int nf = 0; nf < 2; nf++) {
                asm volatile(
                    "mma.sync.aligned.m16n8k16.row.col.f32.f16.f16.f32 "
                    "{%0,%1,%2,%3}, {%4,%5,%6,%7}, {%8,%9}, {%0,%1,%2,%3};"
                    : "+f"(c[mt][nf][0]), "+f"(c[mt][nf][1]),
                      "+f"(c[mt][nf][2]), "+f"(c[mt][nf][3])
                    : "r"(a[mt][0]), "r"(a[mt][1]), "r"(a[mt][2]), "r"(a[mt][3]),
                      "r"(bf[nf][0]), "r"(bf[nf][1]));
            }
    }
}

__device__ __forceinline__ void frag_writeback(float* out, int ldo, int n0,
                                               int wm, int wn, int lane, float c[2][2][4]) {
    const int g = lane >> 2, tq = lane & 3;
#pragma unroll
    for (int mt = 0; mt < 2; mt++)
#pragma unroll
        for (int nf = 0; nf < 2; nf++) {
            int r = wm + mt * 16 + g;
            int cc = n0 + wn + nf * 8 + tq * 2;
            out[(size_t)r * ldo + cc]           = c[mt][nf][0];
            out[(size_t)r * ldo + cc + 1]       = c[mt][nf][1];
            out[(size_t)(r + 8) * ldo + cc]     = c[mt][nf][2];
            out[(size_t)(r + 8) * ldo + cc + 1] = c[mt][nf][3];
        }
}

// ---------------- K1: pipelined gates TC GEMM: M=64, K-chunk 128, grid (32,8) ----------
__global__ void k_tc_gemm2(const __half* __restrict__ A, int lda,
                           const __half* __restrict__ W, int ldw,
                           float* __restrict__ outP, int ldo) {
    __shared__ __align__(16) __half sA[2][64][72];
    __shared__ __align__(16) __half sB[2][64][72];
    const int n0 = blockIdx.x * 64;
    const int kbase = blockIdx.y * 128;
    float* out = outP + (size_t)blockIdx.y * 64 * ldo;
    const int tid = threadIdx.x;
    const int lane = tid & 31;
    const int w = tid >> 5;
    const int wm = (w >> 2) * 32;
    const int wn = (w & 3) * 16;

#pragma unroll
    for (int slab = 0; slab < 2; slab++) {
        const int k0 = kbase + slab * 64;
#pragma unroll
        for (int p = 0; p < 2; p++) {
            int idx = p * 256 + tid;
            int r = idx >> 3, c8 = (idx & 7) * 8;
            *(float4*)&sA[slab][r][c8] = *(const float4*)&A[(size_t)r * lda + k0 + c8];
            *(float4*)&sB[slab][r][c8] = *(const float4*)&W[(size_t)(n0 + r) * ldw + k0 + c8];
        }
    }
    __syncthreads();

    float c[2][2][4];
#pragma unroll
    for (int i = 0; i < 2; i++)
#pragma unroll
        for (int j = 0; j < 2; j++)
#pragma unroll
            for (int q = 0; q < 4; q++) c[i][j][q] = 0.f;
    mma_slab(sA[0], sB[0], wm, wn, lane, c);
    mma_slab(sA[1], sB[1], wm, wn, lane, c);
    frag_writeback(out, ldo, n0, wm, wn, lane, c);
}

// ---------------- K2: lstm (redundant, c double-buffered) + hde TC GEMM, grid 32 ----------
__global__ void k_lstm_hde(const float* __restrict__ b_ih, const float* __restrict__ b_hh,
                           int cur, int t) {
    __shared__ __align__(16) __half A2[2][64][72];
    __shared__ __align__(16) __half Bm[64][72];
    const int bid = blockIdx.x;
    const int nt = bid >> 2, ks = bid & 3;
    const int tid = threadIdx.x;
    const int lane = tid & 31, w = tid >> 5;
    const int wm = (w >> 2) * 32, wn = (w & 3) * 16;
    const int nxt = cur ^ 1;

    for (int i = tid; i < 64 * 128; i += 256) {
        int b = i >> 7, jj = i & 127;
        int j = ks * 128 + jj;
        const float* xgp = g_xg + ((size_t)b * T + t) * G4;
        float gi = b_ih[j]           + b_hh[j]           + xgp[j];
        float gf = b_ih[TRG + j]     + b_hh[TRG + j]     + xgp[TRG + j];
        float gg = b_ih[2 * TRG + j] + b_hh[2 * TRG + j] + xgp[2 * TRG + j];
        float go = b_ih[3 * TRG + j] + b_hh[3 * TRG + j] + xgp[3 * TRG + j];
#pragma unroll
        for (int s8 = 0; s8 < 8; s8++) {
            const float* gp = g_gp8[s8] + b * G4;
            gi += gp[j]; gf += gp[TRG + j]; gg += gp[2 * TRG + j]; go += gp[3 * TRG + j];
        }
        float cn = sigmoidf_(gf) * g_c[cur][b * TRG + j] + sigmoidf_(gi) * tanhf(gg);
        float hn = sigmoidf_(go) * tanhf(cn);
        g_c[nxt][b * TRG + j] = cn;
        g_h[b * TRG + j] = hn;
        __half h16 = __float2half_rn(hn);
        g_x_h[b * 1024 + 512 + j] = h16;
        A2[jj >> 6][b][jj & 63] = h16;
    }
    __syncthreads();
    const int n0 = nt * 64;
    float c[2][2][4];
#pragma unroll
    for (int i = 0; i < 2; i++)
#pragma unroll
        for (int j = 0; j < 2; j++)
#pragma unroll
            for (int q = 0; q < 4; q++) c[i][j][q] = 0.f;
#pragma unroll
    for (int slab = 0; slab < 2; slab++) {
        __syncthreads();
        {
            int rr = tid >> 2;
            int cc = (tid & 3) * 16;
            *(float4*)&Bm[rr][cc] =
                *(const float4*)&g_wde_h[(size_t)(n0 + rr) * TRG + ks * 128 + slab * 64 + cc];
            *(float4*)&Bm[rr][cc + 8] =
                *(const float4*)&g_wde_h[(size_t)(n0 + rr) * TRG + ks * 128 + slab * 64 + cc + 8];
        }
        __syncthreads();
        mma_slab(A2[slab], Bm, wm, wn, lane, c);
    }
    frag_writeback(g_hde4[ks], TRG, n0, wm, wn, lane, c);
}

// ---------------- K3: flash attn — logits + local softmax + cenc partial, grid (16,B) ----
__global__ void k_attn_flash(const float* __restrict__ w_cv, const float* __restrict__ w_warp) {
    __shared__ __align__(16) float sh_hde[TRG], sh_cv[TRG], sh_w[TRG];
    __shared__ float sl[64], se[64];
    const int sb = blockIdx.x, b = blockIdx.y;
    const int tid = threadIdx.x, lane = tid & 31, w = tid >> 5;

    for (int i = tid; i < TRG; i += 256) {
        sh_hde[i] = g_hde4[0][b * TRG + i] + g_hde4[1][b * TRG + i]
                  + g_hde4[2][b * TRG + i] + g_hde4[3][b * TRG + i];
        sh_cv[i]  = w_cv[i];
        sh_w[i]   = w_warp[i];
    }
    __syncthreads();
    const float2* hd2 = (const float2*)sh_hde;
    const float2* cv2 = (const float2*)sh_cv;
    const float2* ww2 = (const float2*)sh_w;
#pragma unroll
    for (int r = 0; r < 8; r++) {
        const int s = sb * 64 + w * 8 + r;
        const float pa = g_pa[b * S + s];
        const __half2* ep2 = (const __half2*)(g_encproj_h + ((size_t)b * S + s) * TRG);
        float acc = 0.f;
#pragma unroll
        for (int p = 0; p < 8; p++) {
            int i2 = lane + p * 32;
            float2 e  = __half22float2(ep2[i2]);
            float2 hd = hd2[i2], cv = cv2[i2], ww = ww2[i2];
            acc = fmaf(tanh_ap(e.x + hd.x + pa * cv.x), ww.x, acc);
            acc = fmaf(tanh_ap(e.y + hd.y + pa * cv.y), ww.y, acc);
        }
        acc = warp_red_sum(acc);
        if (lane == 0) sl[w * 8 + r] = acc;
    }
    __syncthreads();
    float m = sl[0];
#pragma unroll
    for (int i = 1; i < 64; i++) m = fmaxf(m, sl[i]);
    if (tid < 64) se[tid] = __expf(sl[tid] - m);
    __syncthreads();
    if (tid < 64) g_attn[b * S + sb * 64 + tid] = se[tid];
    if (tid == 0) {
        float sum = 0.f;
#pragma unroll
        for (int i = 0; i < 64; i++) sum += se[i];
        g_pm[b * 16 + sb] = m;
        g_ps[b * 16 + sb] = sum;
    }
    const __half2* e2 = (const __half2*)g_enc_h + ((size_t)b * S + sb * 64) * (ENC / 2) + tid;
    float ax = 0.f, ay = 0.f;
#pragma unroll 4
    for (int s = 0; s < 64; s++) {
        float2 f = __half22float2(e2[(size_t)s * (ENC / 2)]);
        float wv = se[s];
        ax = fmaf(wv, f.x, ax);
        ay = fmaf(wv, f.y, ay);
    }
    g_cencP[sb][b * TRG + tid * 2]     = ax;
    g_cencP[sb][b * TRG + tid * 2 + 1] = ay;
}

// ---------------- K4: ha GEMM + pgen + softmax finalize, grid 193 ----------------
__global__ void k_ha_pgen_fin(const float* __restrict__ w_ao, const float* __restrict__ b_ao,
                              const float* __restrict__ input_, const float* __restrict__ w_pt,
                              const float* __restrict__ b_pt, float* __restrict__ out_attn_t,
                              float* __restrict__ out, int t) {
    __shared__ __align__(16) float sX[8][1024];
    __shared__ float sfac[64][16];
    __shared__ float sm_m[64], sm_inv[64];
    const int tid = threadIdx.x;
    if (blockIdx.x < 128) {
        const int jt = blockIdx.x >> 3, bt = blockIdx.x & 7;
        const int j0 = jt * 32, b0 = bt * 8;
        if (tid < 8) {
            int b = b0 + tid;
            float m = g_pm[b * 16];
#pragma unroll
            for (int q = 1; q < 16; q++) m = fmaxf(m, g_pm[b * 16 + q]);
            float tot = 0.f;
#pragma unroll
            for (int q = 0; q < 16; q++) tot += g_ps[b * 16 + q] * __expf(g_pm[b * 16 + q] - m);
            sm_m[tid] = m; sm_inv[tid] = 1.0f / tot;
        }
        __syncthreads();
        if (tid < 128) {
            int bb = tid >> 4, q = tid & 15;
            sfac[bb][q] = __expf(g_pm[(b0 + bb) * 16 + q] - sm_m[bb]) * sm_inv[bb];
        }
        __syncthreads();
        for (int i = tid; i < 8 * 1024; i += 256) {
            int bb = i >> 10, k = i & 1023;
            float v;
            if (k < TRG) {
                int idx = (b0 + bb) * TRG + k;
                v = 0.f;
#pragma unroll
                for (int q = 0; q < 16; q++) v = fmaf(g_cencP[q][idx], sfac[bb][q], v);
            } else {
                v = g_h[(b0 + bb) * TRG + k - TRG];
            }
            sX[bb][k] = v;
        }
        __syncthreads();
        const int warp = tid >> 5, lane = tid & 31;
#pragma unroll
        for (int jj = 0; jj < 4; jj++) {
            const int j = j0 + warp * 4 + jj;
            const float* wrow = w_ao + (size_t)j * 1024;
            float acc[8];
#pragma unroll
            for (int bb = 0; bb < 8; bb++) acc[bb] = 0.f;
#pragma unroll
            for (int i = 0; i < 8; i++) {
                int k = i * 128 + lane * 4;
                float4 wv = *(const float4*)&wrow[k];
#pragma unroll
                for (int bb = 0; bb < 8; bb++) {
                    float4 xv = *(const float4*)&sX[bb][k];
                    acc[bb] += wv.x * xv.x + wv.y * xv.y + wv.z * xv.z + wv.w * xv.w;
                }
            }
#pragma unroll
            for (int bb = 0; bb < 8; bb++) {
                float r = warp_red_sum(acc[bb]);
                if (lane == 0) {
                    r += b_ao[j];
                    int b = b0 + bb;
                    g_ha[b * TRG + j] = r;
                    g_x_h[b * 1024 + j] = __float2half_rn(r);
                    out[OUT_OFF + ((size_t)b * T + t) * TRG + j] = r;
                }
            }
        }
    } else if (blockIdx.x == 128) {
        // pgen: needs per-b scale factors for all 64 b
        if (tid < 64) {
            int b = tid;
            float m = g_pm[b * 16];
#pragma unroll
            for (int q = 1; q < 16; q++) m = fmaxf(m, g_pm[b * 16 + q]);
            float tot = 0.f;
#pragma unroll
            for (int q = 0; q < 16; q++) tot += g_ps[b * 16 + q] * __expf(g_pm[b * 16 + q] - m);
            sm_m[tid] = m; sm_inv[tid] = 1.0f / tot;
        }
        __syncthreads();
        for (int e = tid; e < 64 * 16; e += 256) {
            int b = e >> 4, q = e & 15;
            sfac[b][q] = __expf(g_pm[b * 16 + q] - sm_m[b]) * sm_inv[b];
        }
        __syncthreads();
        const int warp = tid >> 5, lane = tid & 31;
#pragma unroll
        for (int r = 0; r < 8; r++) {
            int b = warp * 8 + r;
            const float* xt = input_ + ((size_t)b * T + t) * IN;
            float acc = 0.f;
            for (int k = lane; k < IN; k += 32)  acc = fmaf(w_pt[k], xt[k], acc);
            for (int k = lane; k < TRG; k += 32) acc = fmaf(w_pt[IN + k], g_h[b * TRG + k], acc);
            for (int k = lane; k < TRG; k += 32) {
                int idx = b * TRG + k;
                float cv = 0.f;
#pragma unroll
                for (int q = 0; q < 16; q++) cv = fmaf(g_cencP[q][idx], sfac[b][q], cv);
                acc = fmaf(w_pt[IN + TRG + k], cv, acc);
            }
            acc = warp_red_sum(acc);
            if (lane == 0) out[PGEN_OFF + (size_t)b * T + t] = sigmoidf_(acc + b_pt[0]);
        }
    } else {
        // finalize softmax for one b: normalize exps, write attn out + pa
        __shared__ float pmS[16], psS[16];
        const int b = blockIdx.x - 129;
        if (tid < 16) { pmS[tid] = g_pm[b * 16 + tid]; psS[tid] = g_ps[b * 16 + tid]; }
        __syncthreads();
        float m = pmS[0];
#pragma unroll
        for (int q = 1; q < 16; q++) m = fmaxf(m, pmS[q]);
        float tot = 0.f;
#pragma unroll
        for (int q = 0; q < 16; q++) tot += psS[q] * __expf(pmS[q] - m);
        const float inv = 1.0f / tot;
        const float f = __expf(pmS[tid >> 4] - m) * inv;   // tid*4..tid*4+3 share sb = tid>>4
        float4 v4 = *(const float4*)&g_attn[b * S + tid * 4];
        v4.x *= f; v4.y *= f; v4.z *= f; v4.w *= f;
        *(float4*)&out_attn_t[(size_t)b * S + tid * 4] = v4;
        float4 p4 = *(const float4*)&g_pa[b * S + tid * 4];
        p4.x += v4.x; p4.y += v4.y; p4.z += v4.z; p4.w += v4.w;
        *(float4*)&g_pa[b * S + tid * 4] = p4;
    }
}

// ---------------- finalize ----------------
__global__ void k_final(float* __restrict__ out, const float* __restrict__ past_dehy) {
    int i = blockIdx.x * blockDim.x + threadIdx.x;
    if (i < B * TRG) {
        out[HT_OFF + i]  = g_h[i];
        out[CT_OFF + i]  = g_c[0][i];   // T even -> final c in buffer 0
        out[HAT_OFF + i] = g_ha[i];
        out[PDH_OFF + i] = past_dehy[i];
    }
    if (i < B * S) out[PAT_OFF + i] = g_pa[i];
    if (i == 0) out[LOSS_OFF] = 0.f;
}

// ---------------- launch ----------------
extern "C" void kernel_launch(void* const* d_in, const int* in_sizes, int n_in,
                              void* d_out, int out_size) {
    const float* input_    = (const float*)d_in[1];
    const float* h0        = (const float*)d_in[2];
    const float* c0        = (const float*)d_in[3];
    const float* h_attn    = (const float*)d_in[4];
    const float* enc       = (const float*)d_in[5];
    const float* past_attn = (const float*)d_in[6];
    const float* past_dehy = (const float*)d_in[7];
    const float* w_ih      = (const float*)d_in[8];
    const float* b_ih      = (const float*)d_in[9];
    const float* w_hh      = (const float*)d_in[10];
    const float* b_hh      = (const float*)d_in[11];
    const float* w_en      = (const float*)d_in[12];
    const float* b_en      = (const float*)d_in[13];
    const float* w_de      = (const float*)d_in[14];
    const float* w_cv      = (const float*)d_in[15];
    const float* w_warp    = (const float*)d_in[16];
    const float* w_ao      = (const float*)d_in[17];
    const float* b_ao      = (const float*)d_in[18];
    const float* w_pt      = (const float*)d_in[19];
    const float* b_pt      = (const float*)d_in[20];
    float* out = (float*)d_out;

    __half *p_enc_h, *p_wen_h, *p_input_h, *p_encproj_h, *p_wihx_h, *p_wr_h, *p_x_h;
    float *p_xg, *p_gp8;
    cudaGetSymbolAddress((void**)&p_enc_h, g_enc_h);
    cudaGetSymbolAddress((void**)&p_wen_h, g_wen_h);
    cudaGetSymbolAddress((void**)&p_input_h, g_input_h);
    cudaGetSymbolAddress((void**)&p_encproj_h, g_encproj_h);
    cudaGetSymbolAddress((void**)&p_wihx_h, g_wihx_h);
    cudaGetSymbolAddress((void**)&p_wr_h, g_wr_h);
    cudaGetSymbolAddress((void**)&p_x_h, g_x_h);
    cudaGetSymbolAddress((void**)&p_xg, g_xg);
    cudaGetSymbolAddress((void**)&p_gp8, g_gp8);

    // setup: 3 launches
    k_setup<<<4096, 256>>>(enc, w_en, input_, w_de, w_ih, w_hh, h0, c0, h_attn, past_attn);
    k_mma<true><<<dim3(512 / 64, (B * S) / 128), 256>>>(p_enc_h, p_wen_h, b_en,
                                                        p_encproj_h, 512, 512);
    k_mma<false><<<dim3(G4 / 64, (B * T) / 128), 256>>>(p_input_h, p_wihx_h, nullptr,
                                                        p_xg, IN, G4);

    for (int t = 0; t < T; t++) {
        int cur = t & 1;
        k_tc_gemm2<<<dim3(32, 8), 256>>>(p_x_h, 1024, p_wr_h, 1024, p_gp8, G4);
        k_lstm_hde<<<32, 256>>>(b_ih, b_hh, cur, t);
        k_attn_flash<<<dim3(16, B), 256>>>(w_cv, w_warp);
        k_ha_pgen_fin<<<193, 256>>>(w_ao, b_ao, input_, w_pt, b_pt,
                                    out + ATTN_OFF + (size_t)t * B * S, out, t);
    }
    k_final<<<(B * S + 255) / 256, 256>>>(out, past_dehy);
}

// round 16
// speedup vs baseline: 1.5201x; 1.5201x over previous
#include <cuda_runtime.h>
#include <cuda_fp16.h>
#include <math.h>

// Problem constants
#define B   64
#define T   100
#define S   1024
#define IN  256
#define TRG 512
#define ENC 512
#define G4  2048   // 4*TRG

// Output layout offsets (floats)
#define OUT_OFF   0
#define HT_OFF    3276800
#define CT_OFF    3309568
#define HAT_OFF   3342336
#define ATTN_OFF  3375104
#define PAT_OFF   9928704
#define PGEN_OFF  9994240
#define PDH_OFF   10000640
#define LOSS_OFF  10033408

// ---------------- device state ----------------
__device__ __align__(16) __half  g_encproj_h[(size_t)B * S * TRG];   // 67 MB
__device__ __align__(16) __half  g_enc_h[(size_t)B * S * ENC];       // 67 MB
__device__ __align__(16) __half  g_wen_h[512 * 512];
__device__ __align__(16) __half  g_input_h[B * T * IN];
__device__ __align__(16) __half  g_wihx_h[G4 * IN];
__device__ __align__(16) __half  g_wr_h[(size_t)G4 * 1024];
__device__ __align__(16) __half  g_wde_h[TRG * TRG];
__device__ __align__(16) __half  g_x_h[B * 1024];                    // [ha | h] fp16
__device__ __align__(16) float   g_xg[(size_t)B * T * G4];
__device__ __align__(16) float g_h[B * TRG];
__device__ __align__(16) float g_c[B * TRG];
__device__ __align__(16) float g_ha[B * TRG];
__device__ __align__(16) float g_pa[B * S];
__device__ __align__(16) float g_gp8[8][B * G4];                     // gates split-K partials
__device__ __align__(16) float g_hde4[4][B * TRG];                   // hde split-K partials
__device__ __align__(16) float g_attn[B * S];                        // unnormalized chunk exps
__device__ __align__(16) float g_pm[B * 16];                         // chunk max
__device__ __align__(16) float g_ps[B * 16];                         // chunk expsum
__device__ __align__(16) float g_cencP[16][B * TRG];                 // cenc chunk partials

__device__ __forceinline__ float warp_red_sum(float v) {
#pragma unroll
    for (int o = 16; o; o >>= 1) v += __shfl_xor_sync(0xffffffffu, v, o);
    return v;
}
__device__ __forceinline__ float sigmoidf_(float x) { return 1.0f / (1.0f + expf(-x)); }
__device__ __forceinline__ float tanh_ap(float x) {
    float y; asm("tanh.approx.f32 %0, %1;" : "=f"(y) : "f"(x)); return y;
}
__device__ __forceinline__ unsigned smem_u32(const void* p) {
    return (unsigned)__cvta_generic_to_shared(p);
}

// ---------------- merged setup ----------------
#define SEG_A 8388608u
#define SEG_B (SEG_A + 65536u)
#define SEG_C (SEG_B + 409600u)
#define SEG_D (SEG_C + 65536u)
#define SEG_E (SEG_D + 131072u)
#define SEG_F (SEG_E + 524288u)
#define SEG_G (SEG_F + 8192u)
#define SEG_H (SEG_G + 16384u)

__device__ __forceinline__ void f2h_unit(const float* __restrict__ src,
                                         __half* __restrict__ dst, unsigned u) {
    float4 v = *(const float4*)&src[(size_t)u * 4];
    __half2* d = (__half2*)&dst[(size_t)u * 4];
    d[0] = __floats2half2_rn(v.x, v.y);
    d[1] = __floats2half2_rn(v.z, v.w);
}

__global__ void k_setup(const float* __restrict__ enc, const float* __restrict__ w_en,
                        const float* __restrict__ input_, const float* __restrict__ w_de,
                        const float* __restrict__ w_ih, const float* __restrict__ w_hh,
                        const float* __restrict__ h0, const float* __restrict__ c0,
                        const float* __restrict__ h_attn, const float* __restrict__ past_attn) {
    for (unsigned u = blockIdx.x * blockDim.x + threadIdx.x; u < SEG_H;
         u += gridDim.x * blockDim.x) {
        if (u < SEG_A) {
            f2h_unit(enc, g_enc_h, u);
        } else if (u < SEG_B) {
            f2h_unit(w_en, g_wen_h, u - SEG_A);
        } else if (u < SEG_C) {
            f2h_unit(input_, g_input_h, u - SEG_B);
        } else if (u < SEG_D) {
            f2h_unit(w_de, g_wde_h, u - SEG_C);
        } else if (u < SEG_E) {
            unsigned v = u - SEG_D;
            unsigned n = v >> 6, c4 = (v & 63u) * 4;
            float4 w = *(const float4*)&w_ih[(size_t)n * (IN + TRG) + c4];
            __half2* d = (__half2*)&g_wihx_h[n * IN + c4];
            d[0] = __floats2half2_rn(w.x, w.y);
            d[1] = __floats2half2_rn(w.z, w.w);
        } else if (u < SEG_F) {
            unsigned v = u - SEG_E;
            unsigned n = v >> 8, k4 = (v & 255u) * 4;
            float4 w = (k4 < TRG) ? *(const float4*)&w_ih[(size_t)n * (IN + TRG) + IN + k4]
                                  : *(const float4*)&w_hh[(size_t)n * TRG + k4 - TRG];
            __half2* d = (__half2*)&g_wr_h[(size_t)n * 1024 + k4];
            d[0] = __floats2half2_rn(w.x, w.y);
            d[1] = __floats2half2_rn(w.z, w.w);
        } else if (u < SEG_G) {
            unsigned v = u - SEG_F;
#pragma unroll
            for (int e = 0; e < 4; e++) {
                int i = v * 4 + e;
                float hv = h0[i], cv = c0[i], av = h_attn[i];
                g_h[i] = hv; g_c[i] = cv; g_ha[i] = av;
                int b = i >> 9, j = i & 511;
                g_x_h[b * 1024 + j]       = __float2half_rn(av);
                g_x_h[b * 1024 + 512 + j] = __float2half_rn(hv);
            }
        } else {
            unsigned v = u - SEG_G;
            *(float4*)&g_pa[v * 4] = *(const float4*)&past_attn[v * 4];
        }
    }
}

// ---------------- setup fp16 TC GEMM (encproj, xg) ----------------
template<bool OUT16>
__global__ void k_mma(const __half* __restrict__ A, const __half* __restrict__ W,
                      const float* __restrict__ bias, void* __restrict__ Cout,
                      int K, int ldc) {
    __shared__ __align__(16) char smem_raw[128 * 68 * 4];
    __shared__ float sBias[64];
    __half (*sA)[72] = (__half(*)[72])smem_raw;
    __half (*sB)[72] = (__half(*)[72])(smem_raw + 18432);

    const int m0 = blockIdx.y * 128;
    const int n0 = blockIdx.x * 64;
    const int tid = threadIdx.x;
    const int lane = tid & 31;
    const int w = tid >> 5;
    const int wm = (w >> 1) * 32;
    const int wn = (w & 1) * 32;

    if (OUT16 && tid < 64) sBias[tid] = bias[n0 + tid];

    float c[2][4][4];
#pragma unroll
    for (int i = 0; i < 2; i++)
#pragma unroll
        for (int j = 0; j < 4; j++)
#pragma unroll
            for (int q = 0; q < 4; q++) c[i][j][q] = 0.f;

    const int lrow = lane & 15;
    const int lcol = (lane >> 4) * 8;

    for (int k0 = 0; k0 < K; k0 += 64) {
        __syncthreads();
        {
            int r = tid >> 3, cc = (tid & 7) * 8;
#pragma unroll
            for (int p = 0; p < 4; p++)
                *(float4*)&sA[r + p * 32][cc] =
                    *(const float4*)&A[(size_t)(m0 + r + p * 32) * K + k0 + cc];
#pragma unroll
            for (int p = 0; p < 2; p++)
                *(float4*)&sB[r + p * 32][cc] =
                    *(const float4*)&W[(size_t)(n0 + r + p * 32) * K + k0 + cc];
        }
        __syncthreads();
#pragma unroll
        for (int kk = 0; kk < 4; kk++) {
            unsigned a[2][4], bf[4][2];
#pragma unroll
            for (int mt = 0; mt < 2; mt++) {
                unsigned addr = smem_u32(&sA[wm + mt * 16 + lrow][kk * 16 + lcol]);
                asm volatile("ldmatrix.sync.aligned.m8n8.x4.shared.b16 {%0,%1,%2,%3}, [%4];"
                             : "=r"(a[mt][0]), "=r"(a[mt][1]), "=r"(a[mt][2]), "=r"(a[mt][3])
                             : "r"(addr));
            }
#pragma unroll
            for (int bp = 0; bp < 2; bp++) {
                unsigned r0, r1, r2, r3;
                unsigned addr = smem_u32(&sB[wn + bp * 16 + lrow][kk * 16 + lcol]);
                asm volatile("ldmatrix.sync.aligned.m8n8.x4.shared.b16 {%0,%1,%2,%3}, [%4];"
                             : "=r"(r0), "=r"(r1), "=r"(r2), "=r"(r3) : "r"(addr));
                bf[bp * 2 + 0][0] = r0; bf[bp * 2 + 0][1] = r2;
                bf[bp * 2 + 1][0] = r1; bf[bp * 2 + 1][1] = r3;
            }
#pragma unroll
            for (int mt = 0; mt < 2; mt++)
#pragma unroll
                for (int nf = 0; nf < 4; nf++) {
                    asm volatile(
                        "mma.sync.aligned.m16n8k16.row.col.f32.f16.f16.f32 "
                        "{%0,%1,%2,%3}, {%4,%5,%6,%7}, {%8,%9}, {%0,%1,%2,%3};"
                        : "+f"(c[mt][nf][0]), "+f"(c[mt][nf][1]),
                          "+f"(c[mt][nf][2]), "+f"(c[mt][nf][3])
                        : "r"(a[mt][0]), "r"(a[mt][1]), "r"(a[mt][2]), "r"(a[mt][3]),
                          "r"(bf[nf][0]), "r"(bf[nf][1]));
                }
        }
    }
    __syncthreads();
    float (*sO)[68] = (float(*)[68])smem_raw;
    {
        int g = lane >> 2, tq = lane & 3;
#pragma unroll
        for (int mt = 0; mt < 2; mt++)
#pragma unroll
            for (int nf = 0; nf < 4; nf++) {
                int r = wm + mt * 16 + g;
                int cc = wn + (nf >> 1) * 16 + (nf & 1) * 8 + tq * 2;
                sO[r][cc]     = c[mt][nf][0]; sO[r][cc + 1]     = c[mt][nf][1];
                sO[r + 8][cc] = c[mt][nf][2]; sO[r + 8][cc + 1] = c[mt][nf][3];
            }
    }
    __syncthreads();
#pragma unroll
    for (int p = 0; p < 4; p++) {
        int idx = p * 256 + tid;
        int r = idx >> 3, c8 = (idx & 7) * 8;
        if (OUT16) {
            __half* C = (__half*)Cout;
            __half2 h[4];
#pragma unroll
            for (int q = 0; q < 4; q++)
                h[q] = __floats2half2_rn(sO[r][c8 + 2 * q] + sBias[c8 + 2 * q],
                                         sO[r][c8 + 2 * q + 1] + sBias[c8 + 2 * q + 1]);
            *(float4*)&C[(size_t)(m0 + r) * ldc + n0 + c8] = *(float4*)h;
        } else {
            float* C = (float*)Cout;
            *(float4*)&C[(size_t)(m0 + r) * ldc + n0 + c8]     = *(float4*)&sO[r][c8];
            *(float4*)&C[(size_t)(m0 + r) * ldc + n0 + c8 + 4] = *(float4*)&sO[r][c8 + 4];
        }
    }
}

// ---------------- shared mma helpers ----------------
__device__ __forceinline__ void mma_slab(const __half (*sA)[72], const __half (*sB)[72],
                                         int wm, int wn, int lane, float c[2][2][4]) {
    const int lrow = lane & 15;
    const int lcol = (lane >> 4) * 8;
#pragma unroll
    for (int kk = 0; kk < 4; kk++) {
        unsigned a[2][4], bf[2][2];
#pragma unroll
        for (int mt = 0; mt < 2; mt++) {
            unsigned addr = smem_u32(&sA[wm + mt * 16 + lrow][kk * 16 + lcol]);
            asm volatile("ldmatrix.sync.aligned.m8n8.x4.shared.b16 {%0,%1,%2,%3}, [%4];"
                         : "=r"(a[mt][0]), "=r"(a[mt][1]), "=r"(a[mt][2]), "=r"(a[mt][3])
                         : "r"(addr));
        }
        {
            unsigned r0, r1, r2, r3;
            unsigned addr = smem_u32(&sB[wn + lrow][kk * 16 + lcol]);
            asm volatile("ldmatrix.sync.aligned.m8n8.x4.shared.b16 {%0,%1,%2,%3}, [%4];"
                         : "=r"(r0), "=r"(r1), "=r"(r2), "=r"(r3) : "r"(addr));
            bf[0][0] = r0; bf[0][1] = r2;
            bf[1][0] = r1; bf[1][1] = r3;
        }
#pragma unroll
        for (int mt = 0; mt < 2; mt++)
#pragma unroll
            for (int nf = 0; nf < 2; nf++) {
                asm volatile(
                    "mma.sync.aligned.m16n8k16.row.col.f32.f16.f16.f32 "
                    "{%0,%1,%2,%3}, {%4,%5,%6,%7}, {%8,%9}, {%0,%1,%2,%3};"
                    : "+f"(c[mt][nf][0]), "+f"(c[mt][nf][1]),
                      "+f"(c[mt][nf][2]), "+f"(c[mt][nf][3])
                    : "r"(a[mt][0]), "r"(a[mt][1]), "r"(a[mt][2]), "r"(a[mt][3]),
                      "r"(bf[nf][0]), "r"(bf[nf][1]));
            }
    }
}

__device__ __forceinline__ void frag_writeback(float* out, int ldo, int n0,
                                               int wm, int wn, int lane, float c[2][2][4]) {
    const int g = lane >> 2, tq = lane & 3;
#pragma unroll
    for (int mt = 0; mt < 2; mt++)
#pragma unroll
        for (int nf = 0; nf < 2; nf++) {
            int r = wm + mt * 16 + g;
            int cc = n0 + wn + nf * 8 + tq * 2;
            out[(size_t)r * ldo + cc]           = c[mt][nf][0];
            out[(size_t)r * ldo + cc + 1]       = c[mt][nf][1];
            out[(size_t)(r + 8) * ldo + cc]     = c[mt][nf][2];
            out[(size_t)(r + 8) * ldo + cc + 1] = c[mt][nf][3];
        }
}

// ---------------- pipelined per-step TC GEMM: M=64, K-chunk 128 (2 slabs, 1 sync) --------
__global__ void k_tc_gemm2(const __half* __restrict__ A, int lda,
                           const __half* __restrict__ W, int ldw,
                           float* __restrict__ outP, int ldo) {
    __shared__ __align__(16) __half sA[2][64][72];
    __shared__ __align__(16) __half sB[2][64][72];
    const int n0 = blockIdx.x * 64;
    const int kbase = blockIdx.y * 128;
    float* out = outP + (size_t)blockIdx.y * 64 * ldo;
    const int tid = threadIdx.x;
    const int lane = tid & 31;
    const int w = tid >> 5;
    const int wm = (w >> 2) * 32;
    const int wn = (w & 3) * 16;

#pragma unroll
    for (int slab = 0; slab < 2; slab++) {
        const int k0 = kbase + slab * 64;
#pragma unroll
        for (int p = 0; p < 2; p++) {
            int idx = p * 256 + tid;
            int r = idx >> 3, c8 = (idx & 7) * 8;
            *(float4*)&sA[slab][r][c8] = *(const float4*)&A[(size_t)r * lda + k0 + c8];
            *(float4*)&sB[slab][r][c8] = *(const float4*)&W[(size_t)(n0 + r) * ldw + k0 + c8];
        }
    }
    __syncthreads();

    float c[2][2][4];
#pragma unroll
    for (int i = 0; i < 2; i++)
#pragma unroll
        for (int j = 0; j < 2; j++)
#pragma unroll
            for (int q = 0; q < 4; q++) c[i][j][q] = 0.f;
    mma_slab(sA[0], sB[0], wm, wn, lane, c);
    mma_slab(sA[1], sB[1], wm, wn, lane, c);
    frag_writeback(out, ldo, n0, wm, wn, lane, c);
}

// ---------------- K2: LSTM pointwise (sums 8 partials + xg), grid 128 ----------------
__global__ void k_lstm(const float* __restrict__ b_ih, const float* __restrict__ b_hh, int t) {
    int idx = blockIdx.x * 256 + threadIdx.x;
    int b = idx >> 9, j = idx & 511;
    const float* xgp = g_xg + ((size_t)b * T + t) * G4;
    float gi = b_ih[j]           + b_hh[j]           + xgp[j];
    float gf = b_ih[TRG + j]     + b_hh[TRG + j]     + xgp[TRG + j];
    float gg = b_ih[2 * TRG + j] + b_hh[2 * TRG + j] + xgp[2 * TRG + j];
    float go = b_ih[3 * TRG + j] + b_hh[3 * TRG + j] + xgp[3 * TRG + j];
#pragma unroll
    for (int s = 0; s < 8; s++) {
        const float* gp = g_gp8[s] + b * G4;
        gi += gp[j]; gf += gp[TRG + j]; gg += gp[2 * TRG + j]; go += gp[3 * TRG + j];
    }
    float cn = sigmoidf_(gf) * g_c[idx] + sigmoidf_(gi) * tanhf(gg);
    float hn = sigmoidf_(go) * tanhf(cn);
    g_c[idx] = cn;
    g_h[idx] = hn;
    g_x_h[b * 1024 + 512 + j] = __float2half_rn(hn);
}

// ---------------- K3: flash attn — logits + chunk softmax + cenc partial, grid (16,B) ----
__global__ void k_attn_flash(const float* __restrict__ w_cv, const float* __restrict__ w_warp) {
    __shared__ __align__(16) float sh_hde[TRG], sh_cv[TRG], sh_w[TRG];
    __shared__ float sl[64], se[64];
    const int sb = blockIdx.x, b = blockIdx.y;
    const int tid = threadIdx.x, lane = tid & 31, w = tid >> 5;

    for (int i = tid; i < TRG; i += 256) {
        sh_hde[i] = g_hde4[0][b * TRG + i] + g_hde4[1][b * TRG + i]
                  + g_hde4[2][b * TRG + i] + g_hde4[3][b * TRG + i];
        sh_cv[i]  = w_cv[i];
        sh_w[i]   = w_warp[i];
    }
    __syncthreads();
    const float2* hd2 = (const float2*)sh_hde;
    const float2* cv2 = (const float2*)sh_cv;
    const float2* ww2 = (const float2*)sh_w;
#pragma unroll
    for (int r = 0; r < 8; r++) {
        const int s = sb * 64 + w * 8 + r;
        const float pa = g_pa[b * S + s];
        const __half2* ep2 = (const __half2*)(g_encproj_h + ((size_t)b * S + s) * TRG);
        float acc = 0.f;
#pragma unroll
        for (int p = 0; p < 8; p++) {
            int i2 = lane + p * 32;
            float2 e  = __half22float2(ep2[i2]);
            float2 hd = hd2[i2], cv = cv2[i2], ww = ww2[i2];
            acc = fmaf(tanh_ap(e.x + hd.x + pa * cv.x), ww.x, acc);
            acc = fmaf(tanh_ap(e.y + hd.y + pa * cv.y), ww.y, acc);
        }
        acc = warp_red_sum(acc);
        if (lane == 0) sl[w * 8 + r] = acc;
    }
    __syncthreads();
    float m = sl[0];
#pragma unroll
    for (int i = 1; i < 64; i++) m = fmaxf(m, sl[i]);
    if (tid < 64) se[tid] = __expf(sl[tid] - m);
    __syncthreads();
    if (tid < 64) g_attn[b * S + sb * 64 + tid] = se[tid];
    if (tid == 0) {
        float sum = 0.f;
#pragma unroll
        for (int i = 0; i < 64; i++) sum += se[i];
        g_pm[b * 16 + sb] = m;
        g_ps[b * 16 + sb] = sum;
    }
    const __half2* e2 = (const __half2*)g_enc_h + ((size_t)b * S + sb * 64) * (ENC / 2) + tid;
    float ax = 0.f, ay = 0.f;
#pragma unroll 4
    for (int s = 0; s < 64; s++) {
        float2 f = __half22float2(e2[(size_t)s * (ENC / 2)]);
        float wv = se[s];
        ax = fmaf(wv, f.x, ax);
        ay = fmaf(wv, f.y, ay);
    }
    g_cencP[sb][b * TRG + tid * 2]     = ax;
    g_cencP[sb][b * TRG + tid * 2 + 1] = ay;
}

// ---------------- K4: ha GEMM + pgen + softmax finalize, grid 193 ----------------
__global__ void k_ha_pgen_fin(const float* __restrict__ w_ao, const float* __restrict__ b_ao,
                              const float* __restrict__ input_, const float* __restrict__ w_pt,
                              const float* __restrict__ b_pt, float* __restrict__ out_attn_t,
                              float* __restrict__ out, int t) {
    __shared__ __align__(16) float sX[8][1024];
    __shared__ float sfac[64][16];
    __shared__ float sm_m[64], sm_inv[64];
    const int tid = threadIdx.x;
    if (blockIdx.x < 128) {
        const int jt = blockIdx.x >> 3, bt = blockIdx.x & 7;
        const int j0 = jt * 32, b0 = bt * 8;
        if (tid < 8) {
            int b = b0 + tid;
            float m = g_pm[b * 16];
#pragma unroll
            for (int q = 1; q < 16; q++) m = fmaxf(m, g_pm[b * 16 + q]);
            float tot = 0.f;
#pragma unroll
            for (int q = 0; q < 16; q++) tot += g_ps[b * 16 + q] * __expf(g_pm[b * 16 + q] - m);
            sm_m[tid] = m; sm_inv[tid] = 1.0f / tot;
        }
        __syncthreads();
        if (tid < 128) {
            int bb = tid >> 4, q = tid & 15;
            sfac[bb][q] = __expf(g_pm[(b0 + bb) * 16 + q] - sm_m[bb]) * sm_inv[bb];
        }
        __syncthreads();
        for (int i = tid; i < 8 * 1024; i += 256) {
            int bb = i >> 10, k = i & 1023;
            float v;
            if (k < TRG) {
                int idx = (b0 + bb) * TRG + k;
                v = 0.f;
#pragma unroll
                for (int q = 0; q < 16; q++) v = fmaf(g_cencP[q][idx], sfac[bb][q], v);
            } else {
                v = g_h[(b0 + bb) * TRG + k - TRG];
            }
            sX[bb][k] = v;
        }
        __syncthreads();
        const int warp = tid >> 5, lane = tid & 31;
#pragma unroll
        for (int jj = 0; jj < 4; jj++) {
            const int j = j0 + warp * 4 + jj;
            const float* wrow = w_ao + (size_t)j * 1024;
            float acc[8];
#pragma unroll
            for (int bb = 0; bb < 8; bb++) acc[bb] = 0.f;
#pragma unroll
            for (int i = 0; i < 8; i++) {
                int k = i * 128 + lane * 4;
                float4 wv = *(const float4*)&wrow[k];
#pragma unroll
                for (int bb = 0; bb < 8; bb++) {
                    float4 xv = *(const float4*)&sX[bb][k];
                    acc[bb] += wv.x * xv.x + wv.y * xv.y + wv.z * xv.z + wv.w * xv.w;
                }
            }
#pragma unroll
            for (int bb = 0; bb < 8; bb++) {
                float r = warp_red_sum(acc[bb]);
                if (lane == 0) {
                    r += b_ao[j];
                    int b = b0 + bb;
                    g_ha[b * TRG + j] = r;
                    g_x_h[b * 1024 + j] = __float2half_rn(r);
                    out[OUT_OFF + ((size_t)b * T + t) * TRG + j] = r;
                }
            }
        }
    } else if (blockIdx.x == 128) {
        if (tid < 64) {
            int b = tid;
            float m = g_pm[b * 16];
#pragma unroll
            for (int q = 1; q < 16; q++) m = fmaxf(m, g_pm[b * 16 + q]);
            float tot = 0.f;
#pragma unroll
            for (int q = 0; q < 16; q++) tot += g_ps[b * 16 + q] * __expf(g_pm[b * 16 + q] - m);
            sm_m[tid] = m; sm_inv[tid] = 1.0f / tot;
        }
        __syncthreads();
        for (int e = tid; e < 64 * 16; e += 256) {
            int b = e >> 4, q = e & 15;
            sfac[b][q] = __expf(g_pm[b * 16 + q] - sm_m[b]) * sm_inv[b];
        }
        __syncthreads();
        const int warp = tid >> 5, lane = tid & 31;
#pragma unroll
        for (int r = 0; r < 8; r++) {
            int b = warp * 8 + r;
            const float* xt = input_ + ((size_t)b * T + t) * IN;
            float acc = 0.f;
            for (int k = lane; k < IN; k += 32)  acc = fmaf(w_pt[k], xt[k], acc);
            for (int k = lane; k < TRG; k += 32) acc = fmaf(w_pt[IN + k], g_h[b * TRG + k], acc);
            for (int k = lane; k < TRG; k += 32) {
                int idx = b * TRG + k;
                float cv = 0.f;
#pragma unroll
                for (int q = 0; q < 16; q++) cv = fmaf(g_cencP[q][idx], sfac[b][q], cv);
                acc = fmaf(w_pt[IN + TRG + k], cv, acc);
            }
            acc = warp_red_sum(acc);
            if (lane == 0) out[PGEN_OFF + (size_t)b * T + t] = sigmoidf_(acc + b_pt[0]);
        }
    } else {
        __shared__ float pmS[16], psS[16];
        const int b = blockIdx.x - 129;
        if (tid < 16) { pmS[tid] = g_pm[b * 16 + tid]; psS[tid] = g_ps[b * 16 + tid]; }
        __syncthreads();
        float m = pmS[0];
#pragma unroll
        for (int q = 1; q < 16; q++) m = fmaxf(m, pmS[q]);
        float tot = 0.f;
#pragma unroll
        for (int q = 0; q < 16; q++) tot += psS[q] * __expf(pmS[q] - m);
        const float inv = 1.0f / tot;
        const float f = __expf(pmS[tid >> 4] - m) * inv;
        float4 v4 = *(const float4*)&g_attn[b * S + tid * 4];
        v4.x *= f; v4.y *= f; v4.z *= f; v4.w *= f;
        *(float4*)&out_attn_t[(size_t)b * S + tid * 4] = v4;
        float4 p4 = *(const float4*)&g_pa[b * S + tid * 4];
        p4.x += v4.x; p4.y += v4.y; p4.z += v4.z; p4.w += v4.w;
        *(float4*)&g_pa[b * S + tid * 4] = p4;
    }
}

// ---------------- finalize ----------------
__global__ void k_final(float* __restrict__ out, const float* __restrict__ past_dehy) {
    int i = blockIdx.x * blockDim.x + threadIdx.x;
    if (i < B * TRG) {
        out[HT_OFF + i]  = g_h[i];
        out[CT_OFF + i]  = g_c[i];
        out[HAT_OFF + i] = g_ha[i];
        out[PDH_OFF + i] = past_dehy[i];
    }
    if (i < B * S) out[PAT_OFF + i] = g_pa[i];
    if (i == 0) out[LOSS_OFF] = 0.f;
}

// ---------------- launch ----------------
extern "C" void kernel_launch(void* const* d_in, const int* in_sizes, int n_in,
                              void* d_out, int out_size) {
    const float* input_    = (const float*)d_in[1];
    const float* h0        = (const float*)d_in[2];
    const float* c0        = (const float*)d_in[3];
    const float* h_attn    = (const float*)d_in[4];
    const float* enc       = (const float*)d_in[5];
    const float* past_attn = (const float*)d_in[6];
    const float* past_dehy = (const float*)d_in[7];
    const float* w_ih      = (const float*)d_in[8];
    const float* b_ih      = (const float*)d_in[9];
    const float* w_hh      = (const float*)d_in[10];
    const float* b_hh      = (const float*)d_in[11];
    const float* w_en      = (const float*)d_in[12];
    const float* b_en      = (const float*)d_in[13];
    const float* w_de      = (const float*)d_in[14];
    const float* w_cv      = (const float*)d_in[15];
    const float* w_warp    = (const float*)d_in[16];
    const float* w_ao      = (const float*)d_in[17];
    const float* b_ao      = (const float*)d_in[18];
    const float* w_pt      = (const float*)d_in[19];
    const float* b_pt      = (const float*)d_in[20];
    float* out = (float*)d_out;

    __half *p_enc_h, *p_wen_h, *p_input_h, *p_encproj_h, *p_wihx_h, *p_wr_h, *p_wde_h, *p_x_h;
    float *p_xg, *p_gp8, *p_hde4;
    cudaGetSymbolAddress((void**)&p_enc_h, g_enc_h);
    cudaGetSymbolAddress((void**)&p_wen_h, g_wen_h);
    cudaGetSymbolAddress((void**)&p_input_h, g_input_h);
    cudaGetSymbolAddress((void**)&p_encproj_h, g_encproj_h);
    cudaGetSymbolAddress((void**)&p_wihx_h, g_wihx_h);
    cudaGetSymbolAddress((void**)&p_wr_h, g_wr_h);
    cudaGetSymbolAddress((void**)&p_wde_h, g_wde_h);
    cudaGetSymbolAddress((void**)&p_x_h, g_x_h);
    cudaGetSymbolAddress((void**)&p_xg, g_xg);
    cudaGetSymbolAddress((void**)&p_gp8, g_gp8);
    cudaGetSymbolAddress((void**)&p_hde4, g_hde4);

    // setup: 3 launches
    k_setup<<<4096, 256>>>(enc, w_en, input_, w_de, w_ih, w_hh, h0, c0, h_attn, past_attn);
    k_mma<true><<<dim3(512 / 64, (B * S) / 128), 256>>>(p_enc_h, p_wen_h, b_en,
                                                        p_encproj_h, 512, 512);
    k_mma<false><<<dim3(G4 / 64, (B * T) / 128), 256>>>(p_input_h, p_wihx_h, nullptr,
                                                        p_xg, IN, G4);

    for (int t = 0; t < T; t++) {
        k_tc_gemm2<<<dim3(32, 8), 256>>>(p_x_h, 1024, p_wr_h, 1024, p_gp8, G4);
        k_lstm<<<128, 256>>>(b_ih, b_hh, t);
        k_tc_gemm2<<<dim3(8, 4), 256>>>(p_x_h + 512, 1024, p_wde_h, 512, p_hde4, TRG);
        k_attn_flash<<<dim3(16, B), 256>>>(w_cv, w_warp);
        k_ha_pgen_fin<<<193, 256>>>(w_ao, b_ao, input_, w_pt, b_pt,
                                    out + ATTN_OFF + (size_t)t * B * S, out, t);
    }
    k_final<<<(B * S + 255) / 256, 256>>>(out, past_dehy);
}